// round 6
// baseline (speedup 1.0000x reference)
#include <cuda_runtime.h>
#include <cstdint>

// Problem constants
#define TOK 8192      // b*n tokens
#define D   1024
#define H   8
#define E   16
#define CS  2048
#define COLS (H*E)     // 128 projection columns
#define CPAIR (COLS/2) // 64 column pairs
#define NCP (CS/2)     // 1024 code pairs per head

typedef unsigned long long u64;

// -------- device scratch (static; no allocations allowed) --------
__device__ float g_S[COLS];                           // column sums of W
__device__ __align__(16) float2 g_Wp[D * CPAIR];      // W' = W - S/D, [d][colpair]     (512 KB)
__device__ __align__(16) float2 g_cbp[H * NCP * E];   // normalized cb, code-pair packed (1 MB)
__device__ __align__(16) float  g_P[TOK * COLS];      // projections [t][h*16+e]         (4 MB)

// -------- f32x2 helpers --------
__device__ __forceinline__ u64 pk2(float lo, float hi) {
    u64 r; asm("mov.b64 %0, {%1,%2};" : "=l"(r) : "f"(lo), "f"(hi)); return r;
}
__device__ __forceinline__ void upk2(float& lo, float& hi, u64 v) {
    asm("mov.b64 {%0,%1}, %2;" : "=f"(lo), "=f"(hi) : "l"(v));
}
#define FMA2(acc, a, b) asm("fma.rn.f32x2 %0, %1, %2, %0;" : "+l"(acc) : "l"(a), "l"(b))

// -------- 1: column sums S[h,e] = sum_d W[h,d,e] --------
__global__ void prepS_kernel(const float* __restrict__ W) {
    int col = blockIdx.x;            // h*16+e, 128 blocks
    int h = col >> 4, e = col & 15;
    float s = 0.f;
    for (int d = threadIdx.x; d < D; d += 256)
        s += W[(h * D + d) * E + e];
    __shared__ float red[256];
    red[threadIdx.x] = s;
    __syncthreads();
    for (int off = 128; off > 0; off >>= 1) {
        if (threadIdx.x < off) red[threadIdx.x] += red[threadIdx.x + off];
        __syncthreads();
    }
    if (threadIdx.x == 0) g_S[col] = red[0];
}

// -------- 2: W'[d][cp] = (W - S/D) packed as column-pairs --------
__global__ void prepW_kernel(const float* __restrict__ W) {
    int i = blockIdx.x * 256 + threadIdx.x;   // 65536 = D*CPAIR
    int d = i >> 6, cp = i & 63;
    int h = cp >> 3, ep = cp & 7;
    const float invD = 1.0f / 1024.0f;
    float w0 = W[(h * D + d) * E + 2 * ep]     - g_S[h * E + 2 * ep]     * invD;
    float w1 = W[(h * D + d) * E + 2 * ep + 1] - g_S[h * E + 2 * ep + 1] * invD;
    g_Wp[i] = make_float2(w0, w1);
}

// -------- 3: normalized codebook, code-pair packed --------
// g_cbp[(h*NCP+cp)*E + e] = (cbn[2cp][e], cbn[2cp+1][e])
__global__ void prepCB_kernel(const float* __restrict__ CB) {
    int i = blockIdx.x * 256 + threadIdx.x;   // 8192 = H*NCP
    const float4* a4 = (const float4*)(CB + (size_t)i * 2 * E);
    float4 va[4], vb[4];
#pragma unroll
    for (int k = 0; k < 4; ++k) va[k] = a4[k];
#pragma unroll
    for (int k = 0; k < 4; ++k) vb[k] = a4[4 + k];
    float sa = 0.f, sb = 0.f;
#pragma unroll
    for (int k = 0; k < 4; ++k) {
        sa += va[k].x * va[k].x + va[k].y * va[k].y + va[k].z * va[k].z + va[k].w * va[k].w;
        sb += vb[k].x * vb[k].x + vb[k].y * vb[k].y + vb[k].z * vb[k].z + vb[k].w * vb[k].w;
    }
    float ra = 1.0f / sqrtf(sa + 1e-12f);
    float rb = 1.0f / sqrtf(sb + 1e-12f);
    float2* out = g_cbp + (size_t)i * E;
    const float* a = (const float*)va;
    const float* b = (const float*)vb;
#pragma unroll
    for (int e = 0; e < E; ++e)
        out[e] = make_float2(a[e] * ra, b[e] * rb);
}

// -------- 4: projection GEMM, f32x2, both operands staged in smem --------
// CTA: 32 tokens. Thread: tg = tid&7 -> tokens tg,tg+8,tg+16,tg+24;
//                         cg = tid>>3 -> colpairs 2cg,2cg+1 (cols 4cg..4cg+3).
__global__ __launch_bounds__(256) void proj_kernel(const float* __restrict__ x) {
    __shared__ u64    xs[32][33];   // [dd][tok] duplicated (x,x); pad 33 -> conflict-free
    __shared__ float2 Ws[32][64];   // [dd][cp]
    int t0 = blockIdx.x * 32;
    int tid = threadIdx.x;
    int tg = tid & 7;
    int cg = tid >> 3;
    u64 acc[4][2];
#pragma unroll
    for (int i = 0; i < 4; ++i) { acc[i][0] = 0ull; acc[i][1] = 0ull; }

    for (int ch = 0; ch < 32; ++ch) {
        int base = ch * 32;
        // stage x chunk: 32 tok x 32 dd
#pragma unroll
        for (int j = 0; j < 4; ++j) {
            int idx = j * 256 + tid;          // 0..1023
            int t = idx >> 5, dd = idx & 31;
            float v = x[(size_t)(t0 + t) * D + base + dd];
            xs[dd][t] = pk2(v, v);
        }
        // stage W chunk: 32 dd x 64 colpairs
#pragma unroll
        for (int j = 0; j < 8; ++j) {
            int idx = j * 256 + tid;          // 0..2047
            int dd = idx >> 6, cp = idx & 63;
            Ws[dd][cp] = g_Wp[(size_t)(base + dd) * CPAIR + cp];
        }
        __syncthreads();
#pragma unroll 8
        for (int dd = 0; dd < 32; ++dd) {
            ulonglong2 w = *(const ulonglong2*)&Ws[dd][2 * cg];
#pragma unroll
            for (int i = 0; i < 4; ++i) {
                u64 xv = xs[dd][tg + 8 * i];
                FMA2(acc[i][0], w.x, xv);
                FMA2(acc[i][1], w.y, xv);
            }
        }
        __syncthreads();
    }
#pragma unroll
    for (int i = 0; i < 4; ++i) {
        float4 o;
        upk2(o.x, o.y, acc[i][0]);
        upk2(o.z, o.w, acc[i][1]);
        *(float4*)&g_P[(size_t)(t0 + tg + 8 * i) * COLS + 4 * cg] = o;
    }
}

// -------- 5: similarity scan + argmax, f32x2 code-pair packed --------
// Block = 8 warps, ONE head per block (all warps share the head's 128KB packed cb).
// Warp = 2 tokens; 32 lanes split the 1024 code pairs (lane scans cp = it*32+lane).
__global__ __launch_bounds__(256) void sim_kernel(float* __restrict__ out) {
    int wid = threadIdx.x >> 5;
    int lane = threadIdx.x & 31;
    int h = blockIdx.x >> 9;                 // 512 blocks per head
    int tp = (blockIdx.x & 511) * 8 + wid;   // token pair 0..4095
    int t0 = tp * 2;

    // load + duplicate q for the 2 tokens (16 u64 each)
    u64 qd0[16], qd1[16];
    {
        const float4* q4 = (const float4*)&g_P[(size_t)t0 * COLS + h * E];
#pragma unroll
        for (int k = 0; k < 4; ++k) {
            float4 v = q4[k];
            qd0[4 * k + 0] = pk2(v.x, v.x);
            qd0[4 * k + 1] = pk2(v.y, v.y);
            qd0[4 * k + 2] = pk2(v.z, v.z);
            qd0[4 * k + 3] = pk2(v.w, v.w);
        }
        q4 = (const float4*)&g_P[(size_t)(t0 + 1) * COLS + h * E];
#pragma unroll
        for (int k = 0; k < 4; ++k) {
            float4 v = q4[k];
            qd1[4 * k + 0] = pk2(v.x, v.x);
            qd1[4 * k + 1] = pk2(v.y, v.y);
            qd1[4 * k + 2] = pk2(v.z, v.z);
            qd1[4 * k + 3] = pk2(v.w, v.w);
        }
    }

    const ulonglong2* cbp2 = (const ulonglong2*)(g_cbp + (size_t)h * NCP * E);

    float best0 = -3.402823466e38f, best1 = -3.402823466e38f;
    int idx0 = 0, idx1 = 0;

    for (int it = 0; it < 32; ++it) {
        int cp = it * 32 + lane;             // this lane's code pair
        const ulonglong2* row = cbp2 + (size_t)cp * 8;   // 16 float2 = 8 x 16B
        u64 acc0 = 0ull, acc1 = 0ull;
#pragma unroll
        for (int k = 0; k < 8; ++k) {
            ulonglong2 cc = row[k];          // e=2k and e=2k+1, both codes of the pair
            FMA2(acc0, cc.x, qd0[2 * k]);
            FMA2(acc1, cc.x, qd1[2 * k]);
            FMA2(acc0, cc.y, qd0[2 * k + 1]);
            FMA2(acc1, cc.y, qd1[2 * k + 1]);
        }
        float a, b;
        upk2(a, b, acc0);
        float m = fmaxf(a, b);
        if (m > best0) { best0 = m; idx0 = 2 * cp + (b > a ? 1 : 0); }
        upk2(a, b, acc1);
        m = fmaxf(a, b);
        if (m > best1) { best1 = m; idx1 = 2 * cp + (b > a ? 1 : 0); }
    }

    // warp argmax reduce (tie -> smaller index, matching argmax-first semantics)
    {
        float b0 = best0; int i0 = idx0;
        float b1 = best1; int i1 = idx1;
#pragma unroll
        for (int off = 16; off > 0; off >>= 1) {
            float ob = __shfl_xor_sync(0xffffffffu, b0, off);
            int oi = __shfl_xor_sync(0xffffffffu, i0, off);
            if (ob > b0 || (ob == b0 && oi < i0)) { b0 = ob; i0 = oi; }
            ob = __shfl_xor_sync(0xffffffffu, b1, off);
            oi = __shfl_xor_sync(0xffffffffu, i1, off);
            if (ob > b1 || (ob == b1 && oi < i1)) { b1 = ob; i1 = oi; }
        }
        if (lane == 0) {
            out[(size_t)t0 * H + h]       = (float)i0;
            out[(size_t)(t0 + 1) * H + h] = (float)i1;
        }
    }
}

extern "C" void kernel_launch(void* const* d_in, const int* in_sizes, int n_in,
                              void* d_out, int out_size) {
    const float* x = nullptr;
    const float* W = nullptr;
    const float* CB = nullptr;
    for (int i = 0; i < n_in; ++i) {
        long s = (long)in_sizes[i];
        if (s == 8388608L || s == 33554432L)      x  = (const float*)d_in[i];
        else if (s == 131072L || s == 524288L)    W  = (const float*)d_in[i];
        else if (s == 262144L || s == 1048576L)   CB = (const float*)d_in[i];
    }
    if (!x || !W || !CB) {
        if (n_in >= 3) {
            x  = (const float*)d_in[0];
            W  = (const float*)d_in[1];
            CB = (const float*)d_in[2];
        }
    }
    prepS_kernel<<<128, 256>>>(W);
    prepW_kernel<<<256, 256>>>(W);
    prepCB_kernel<<<32, 256>>>(CB);
    proj_kernel<<<256, 256>>>(x);
    sim_kernel<<<4096, 256>>>((float*)d_out);
}

// round 7
// speedup vs baseline: 2.5584x; 2.5584x over previous
#include <cuda_runtime.h>
#include <cstdint>

// Problem constants
#define TOK 8192      // b*n tokens
#define D   1024
#define H   8
#define E   16
#define CS  2048
#define COLS (H*E)     // 128 projection columns
#define CPAIR (COLS/2) // 64 column pairs
#define NCP (CS/2)     // 1024 code pairs per head

typedef unsigned long long u64;

// -------- device scratch (static; no allocations allowed) --------
__device__ float g_S[COLS];                           // column sums of W
__device__ __align__(16) float2 g_Wp[D * CPAIR];      // W' = W - S/D, [d][colpair]      (512 KB)
__device__ __align__(16) float2 g_cbp[H * NCP * E];   // normalized cb, code-pair packed (1 MB)
__device__ __align__(16) float  g_P[TOK * COLS];      // projections [t][h*16+e]         (4 MB)

// -------- f32x2 helpers --------
__device__ __forceinline__ u64 pk2(float lo, float hi) {
    u64 r; asm("mov.b64 %0, {%1,%2};" : "=l"(r) : "f"(lo), "f"(hi)); return r;
}
__device__ __forceinline__ void upk2(float& lo, float& hi, u64 v) {
    asm("mov.b64 {%0,%1}, %2;" : "=f"(lo), "=f"(hi) : "l"(v));
}
#define FMA2(acc, a, b) asm("fma.rn.f32x2 %0, %1, %2, %0;" : "+l"(acc) : "l"(a), "l"(b))

// -------- 1: column sums S[h,e] = sum_d W[h,d,e] --------
__global__ void prepS_kernel(const float* __restrict__ W) {
    int col = blockIdx.x;            // h*16+e, 128 blocks
    int h = col >> 4, e = col & 15;
    float s = 0.f;
    for (int d = threadIdx.x; d < D; d += 256)
        s += W[(h * D + d) * E + e];
    __shared__ float red[256];
    red[threadIdx.x] = s;
    __syncthreads();
    for (int off = 128; off > 0; off >>= 1) {
        if (threadIdx.x < off) red[threadIdx.x] += red[threadIdx.x + off];
        __syncthreads();
    }
    if (threadIdx.x == 0) g_S[col] = red[0];
}

// -------- 2: W'[d][cp] = (W - S/D) packed as column-pairs --------
__global__ void prepW_kernel(const float* __restrict__ W) {
    int i = blockIdx.x * 256 + threadIdx.x;   // 65536 = D*CPAIR
    int d = i >> 6, cp = i & 63;
    int h = cp >> 3, ep = cp & 7;
    const float invD = 1.0f / 1024.0f;
    float w0 = W[(h * D + d) * E + 2 * ep]     - g_S[h * E + 2 * ep]     * invD;
    float w1 = W[(h * D + d) * E + 2 * ep + 1] - g_S[h * E + 2 * ep + 1] * invD;
    g_Wp[i] = make_float2(w0, w1);
}

// -------- 3: normalized codebook, code-pair packed --------
// g_cbp[(h*NCP+cp)*E + e] = (cbn[2cp][e], cbn[2cp+1][e])
__global__ void prepCB_kernel(const float* __restrict__ CB) {
    int i = blockIdx.x * 256 + threadIdx.x;   // 8192 = H*NCP
    const float4* a4 = (const float4*)(CB + (size_t)i * 2 * E);
    float4 va[4], vb[4];
#pragma unroll
    for (int k = 0; k < 4; ++k) va[k] = a4[k];
#pragma unroll
    for (int k = 0; k < 4; ++k) vb[k] = a4[4 + k];
    float sa = 0.f, sb = 0.f;
#pragma unroll
    for (int k = 0; k < 4; ++k) {
        sa += va[k].x * va[k].x + va[k].y * va[k].y + va[k].z * va[k].z + va[k].w * va[k].w;
        sb += vb[k].x * vb[k].x + vb[k].y * vb[k].y + vb[k].z * vb[k].z + vb[k].w * vb[k].w;
    }
    float ra = 1.0f / sqrtf(sa + 1e-12f);
    float rb = 1.0f / sqrtf(sb + 1e-12f);
    float2* out = g_cbp + (size_t)i * E;
    const float* a = (const float*)va;
    const float* b = (const float*)vb;
#pragma unroll
    for (int e = 0; e < E; ++e)
        out[e] = make_float2(a[e] * ra, b[e] * rb);
}

// -------- 4: projection GEMM, f32x2, smem-staged, 16 tokens x 128 thr --------
// tg = tid&3 -> tokens tg, tg+4, tg+8, tg+12 ; cg = tid>>2 -> colpairs 2cg,2cg+1.
__global__ __launch_bounds__(128) void proj_kernel(const float* __restrict__ x) {
    __shared__ u64    xs[16][33];   // [tok][dd] duplicated (x,x)
    __shared__ float2 Ws[32][64];   // [dd][colpair], 16 KB
    int t0 = blockIdx.x * 16;
    int tid = threadIdx.x;
    int tg = tid & 3;
    int cg = tid >> 2;              // 0..31
    u64 acc[4][2];
#pragma unroll
    for (int i = 0; i < 4; ++i) { acc[i][0] = 0ull; acc[i][1] = 0ull; }

    for (int ch = 0; ch < 32; ++ch) {
        int base = ch * 32;
        // stage x chunk: 16 tok x 32 dd (coalesced over dd)
#pragma unroll
        for (int j = 0; j < 4; ++j) {
            int idx = j * 128 + tid;          // 0..511
            int t = idx >> 5, dd = idx & 31;
            float v = x[(size_t)(t0 + t) * D + base + dd];
            xs[t][dd] = pk2(v, v);
        }
        // stage W chunk: 32 dd x 64 colpairs, 16B units (coalesced)
#pragma unroll
        for (int j = 0; j < 8; ++j) {
            int u = j * 128 + tid;            // 0..1023
            int dd = u >> 5, c2 = u & 31;
            *(ulonglong2*)&Ws[dd][2 * c2] =
                *(const ulonglong2*)&g_Wp[(size_t)(base + dd) * CPAIR + 2 * c2];
        }
        __syncthreads();
#pragma unroll 8
        for (int dd = 0; dd < 32; ++dd) {
            ulonglong2 w = *(const ulonglong2*)&Ws[dd][2 * cg];
#pragma unroll
            for (int i = 0; i < 4; ++i) {
                u64 xv = xs[tg + 4 * i][dd];
                FMA2(acc[i][0], w.x, xv);
                FMA2(acc[i][1], w.y, xv);
            }
        }
        __syncthreads();
    }
#pragma unroll
    for (int i = 0; i < 4; ++i) {
        float4 o;
        upk2(o.x, o.y, acc[i][0]);
        upk2(o.z, o.w, acc[i][1]);
        *(float4*)&g_P[(size_t)(t0 + tg + 4 * i) * COLS + 4 * cg] = o;
    }
}

// -------- 5: similarity scan + argmax, codebook broadcast from smem --------
// Block: 256 thr, one head, 512 tokens (2 per thread). Codebook in 8 chunks of
// 128 code pairs (16 KB smem). Pair index is warp-uniform -> LDS broadcast.
// Thread-local argmax over all 2048 codes; no reduction needed.
__global__ __launch_bounds__(256) void sim_kernel(float* __restrict__ out) {
    __shared__ ulonglong2 cbs[128 * 8];      // 16 KB: pair p -> units p*8..p*8+7
    int tid = threadIdx.x;
    int h = blockIdx.x & 7;
    int tg = blockIdx.x >> 3;                // 0..15
    int t0 = tg * 512 + tid * 2;

    // load + duplicate q for the 2 tokens (16 u64 each)
    u64 qd0[16], qd1[16];
    {
        const float4* q4 = (const float4*)&g_P[(size_t)t0 * COLS + h * E];
#pragma unroll
        for (int k = 0; k < 4; ++k) {
            float4 v = q4[k];
            qd0[4 * k + 0] = pk2(v.x, v.x);
            qd0[4 * k + 1] = pk2(v.y, v.y);
            qd0[4 * k + 2] = pk2(v.z, v.z);
            qd0[4 * k + 3] = pk2(v.w, v.w);
        }
        q4 = (const float4*)&g_P[(size_t)(t0 + 1) * COLS + h * E];
#pragma unroll
        for (int k = 0; k < 4; ++k) {
            float4 v = q4[k];
            qd1[4 * k + 0] = pk2(v.x, v.x);
            qd1[4 * k + 1] = pk2(v.y, v.y);
            qd1[4 * k + 2] = pk2(v.z, v.z);
            qd1[4 * k + 3] = pk2(v.w, v.w);
        }
    }

    const ulonglong2* src = (const ulonglong2*)(g_cbp + (size_t)h * NCP * E);
    float best0 = -3.402823466e38f, best1 = -3.402823466e38f;
    int idx0 = 0, idx1 = 0;

    for (int ch = 0; ch < 8; ++ch) {
        __syncthreads();                     // prev chunk fully consumed
#pragma unroll
        for (int j = 0; j < 4; ++j)          // coalesced 16 KB stage
            cbs[j * 256 + tid] = src[ch * 1024 + j * 256 + tid];
        __syncthreads();

        int cbase = ch * 256;                // first code index of chunk
#pragma unroll 2
        for (int p = 0; p < 128; ++p) {      // warp-uniform -> broadcast LDS
            ulonglong2 c0 = cbs[p * 8 + 0];
            ulonglong2 c1 = cbs[p * 8 + 1];
            ulonglong2 c2 = cbs[p * 8 + 2];
            ulonglong2 c3 = cbs[p * 8 + 3];
            ulonglong2 c4 = cbs[p * 8 + 4];
            ulonglong2 c5 = cbs[p * 8 + 5];
            ulonglong2 c6 = cbs[p * 8 + 6];
            ulonglong2 c7 = cbs[p * 8 + 7];
            u64 acc0 = 0ull, acc1 = 0ull;
            FMA2(acc0, c0.x, qd0[0]);  FMA2(acc1, c0.x, qd1[0]);
            FMA2(acc0, c0.y, qd0[1]);  FMA2(acc1, c0.y, qd1[1]);
            FMA2(acc0, c1.x, qd0[2]);  FMA2(acc1, c1.x, qd1[2]);
            FMA2(acc0, c1.y, qd0[3]);  FMA2(acc1, c1.y, qd1[3]);
            FMA2(acc0, c2.x, qd0[4]);  FMA2(acc1, c2.x, qd1[4]);
            FMA2(acc0, c2.y, qd0[5]);  FMA2(acc1, c2.y, qd1[5]);
            FMA2(acc0, c3.x, qd0[6]);  FMA2(acc1, c3.x, qd1[6]);
            FMA2(acc0, c3.y, qd0[7]);  FMA2(acc1, c3.y, qd1[7]);
            FMA2(acc0, c4.x, qd0[8]);  FMA2(acc1, c4.x, qd1[8]);
            FMA2(acc0, c4.y, qd0[9]);  FMA2(acc1, c4.y, qd1[9]);
            FMA2(acc0, c5.x, qd0[10]); FMA2(acc1, c5.x, qd1[10]);
            FMA2(acc0, c5.y, qd0[11]); FMA2(acc1, c5.y, qd1[11]);
            FMA2(acc0, c6.x, qd0[12]); FMA2(acc1, c6.x, qd1[12]);
            FMA2(acc0, c6.y, qd0[13]); FMA2(acc1, c6.y, qd1[13]);
            FMA2(acc0, c7.x, qd0[14]); FMA2(acc1, c7.x, qd1[14]);
            FMA2(acc0, c7.y, qd0[15]); FMA2(acc1, c7.y, qd1[15]);
            float a, b;
            upk2(a, b, acc0);
            float m = fmaxf(a, b);
            if (m > best0) { best0 = m; idx0 = cbase + 2 * p + (b > a ? 1 : 0); }
            upk2(a, b, acc1);
            m = fmaxf(a, b);
            if (m > best1) { best1 = m; idx1 = cbase + 2 * p + (b > a ? 1 : 0); }
        }
    }

    out[(size_t)t0 * H + h]       = (float)idx0;
    out[(size_t)(t0 + 1) * H + h] = (float)idx1;
}

extern "C" void kernel_launch(void* const* d_in, const int* in_sizes, int n_in,
                              void* d_out, int out_size) {
    const float* x = nullptr;
    const float* W = nullptr;
    const float* CB = nullptr;
    for (int i = 0; i < n_in; ++i) {
        long s = (long)in_sizes[i];
        if (s == 8388608L || s == 33554432L)      x  = (const float*)d_in[i];
        else if (s == 131072L || s == 524288L)    W  = (const float*)d_in[i];
        else if (s == 262144L || s == 1048576L)   CB = (const float*)d_in[i];
    }
    if (!x || !W || !CB) {
        if (n_in >= 3) {
            x  = (const float*)d_in[0];
            W  = (const float*)d_in[1];
            CB = (const float*)d_in[2];
        }
    }
    prepS_kernel<<<128, 256>>>(W);
    prepW_kernel<<<256, 256>>>(W);
    prepCB_kernel<<<32, 256>>>(CB);
    proj_kernel<<<512, 128>>>(x);
    sim_kernel<<<128, 256>>>((float*)d_out);
}

// round 8
// speedup vs baseline: 3.8864x; 1.5191x over previous
#include <cuda_runtime.h>
#include <cstdint>

// Problem constants
#define TOK 8192      // b*n tokens
#define D   1024
#define H   8
#define E   16
#define CS  2048
#define COLS (H*E)     // 128 projection columns
#define CPAIR (COLS/2) // 64 column pairs
#define NCP (CS/2)     // 1024 code pairs per head

typedef unsigned long long u64;

// -------- device scratch (static; no allocations allowed) --------
__device__ float g_S[COLS];                           // column sums of W
__device__ __align__(16) float2 g_Wp[D * CPAIR];      // W' = W - S/D, [d][colpair]      (512 KB)
__device__ __align__(16) float2 g_cbp[H * NCP * E];   // normalized cb, code-pair packed (1 MB)
__device__ __align__(16) float  g_P[TOK * COLS];      // projections [t][h*16+e]         (4 MB)

// -------- f32x2 helpers --------
__device__ __forceinline__ u64 pk2(float lo, float hi) {
    u64 r; asm("mov.b64 %0, {%1,%2};" : "=l"(r) : "f"(lo), "f"(hi)); return r;
}
__device__ __forceinline__ void upk2(float& lo, float& hi, u64 v) {
    asm("mov.b64 {%0,%1}, %2;" : "=f"(lo), "=f"(hi) : "l"(v));
}
#define FMA2(acc, a, b) asm("fma.rn.f32x2 %0, %1, %2, %0;" : "+l"(acc) : "l"(a), "l"(b))
#define ADD2(d, a, b)   asm("add.rn.f32x2 %0, %1, %2;" : "=l"(d) : "l"(a), "l"(b))

// -------- 1: column sums S[h,e] = sum_d W[h,d,e] --------
__global__ void prepS_kernel(const float* __restrict__ W) {
    int col = blockIdx.x;            // h*16+e, 128 blocks
    int h = col >> 4, e = col & 15;
    float s = 0.f;
    for (int d = threadIdx.x; d < D; d += 256)
        s += W[(h * D + d) * E + e];
    __shared__ float red[256];
    red[threadIdx.x] = s;
    __syncthreads();
    for (int off = 128; off > 0; off >>= 1) {
        if (threadIdx.x < off) red[threadIdx.x] += red[threadIdx.x + off];
        __syncthreads();
    }
    if (threadIdx.x == 0) g_S[col] = red[0];
}

// -------- 2: W'[d][cp] = (W - S/D) packed as column-pairs --------
__global__ void prepW_kernel(const float* __restrict__ W) {
    int i = blockIdx.x * 256 + threadIdx.x;   // 65536 = D*CPAIR
    int d = i >> 6, cp = i & 63;
    int h = cp >> 3, ep = cp & 7;
    const float invD = 1.0f / 1024.0f;
    float w0 = W[(h * D + d) * E + 2 * ep]     - g_S[h * E + 2 * ep]     * invD;
    float w1 = W[(h * D + d) * E + 2 * ep + 1] - g_S[h * E + 2 * ep + 1] * invD;
    g_Wp[i] = make_float2(w0, w1);
}

// -------- 3: normalized codebook, code-pair packed --------
// g_cbp[(h*NCP+cp)*E + e] = (cbn[2cp][e], cbn[2cp+1][e])
__global__ void prepCB_kernel(const float* __restrict__ CB) {
    int i = blockIdx.x * 256 + threadIdx.x;   // 8192 = H*NCP
    const float4* a4 = (const float4*)(CB + (size_t)i * 2 * E);
    float4 va[4], vb[4];
#pragma unroll
    for (int k = 0; k < 4; ++k) va[k] = a4[k];
#pragma unroll
    for (int k = 0; k < 4; ++k) vb[k] = a4[4 + k];
    float sa = 0.f, sb = 0.f;
#pragma unroll
    for (int k = 0; k < 4; ++k) {
        sa += va[k].x * va[k].x + va[k].y * va[k].y + va[k].z * va[k].z + va[k].w * va[k].w;
        sb += vb[k].x * vb[k].x + vb[k].y * vb[k].y + vb[k].z * vb[k].z + vb[k].w * vb[k].w;
    }
    float ra = 1.0f / sqrtf(sa + 1e-12f);
    float rb = 1.0f / sqrtf(sb + 1e-12f);
    float2* out = g_cbp + (size_t)i * E;
    const float* a = (const float*)va;
    const float* b = (const float*)vb;
#pragma unroll
    for (int e = 0; e < E; ++e)
        out[e] = make_float2(a[e] * ra, b[e] * rb);
}

// -------- 4: projection GEMM, f32x2, register-prefetch double buffering ----
// CTA: 256 thr, 32 tokens, all 64 colpairs. Thread (tg = tid&7, cg = tid>>3):
// tokens {tg, tg+8, tg+16, tg+24}, colpairs {2cg, 2cg+1}. Chunk = 32 d.
__global__ __launch_bounds__(256) void proj_kernel(const float* __restrict__ x) {
    __shared__ u64    xs[32][34];   // [tok][dd] dup (x,x); pad 34 -> 16B-aligned rows
    __shared__ float2 Ws[32][64];   // [dd][colpair], 16 KB
    int t0 = blockIdx.x * 32;
    int tid = threadIdx.x;
    int tg = tid & 7;
    int cg = tid >> 3;              // 0..31

    // prefetch addressing (constant across chunks)
    int xt  = tid >> 3;             // token this thread stages (0..31)
    int xd4 = tid & 7;              // float4 index within 32-dd chunk
    const float4* xsrc = (const float4*)(x + (size_t)(t0 + xt) * D) + xd4;

    u64 acc[4][2];
#pragma unroll
    for (int i = 0; i < 4; ++i) { acc[i][0] = 0ull; acc[i][1] = 0ull; }

    float4 px;                       // prefetched x (4 floats)
    ulonglong2 pw[4];                // prefetched W (8 float2)

    // prefetch chunk 0
    px = xsrc[0];
#pragma unroll
    for (int j = 0; j < 4; ++j) {
        int q = j * 256 + tid;       // 0..1023
        int dd = q >> 5, c2 = q & 31;
        pw[j] = *(const ulonglong2*)&g_Wp[(size_t)dd * CPAIR + 2 * c2];
    }

    for (int ch = 0; ch < 32; ++ch) {
        if (ch > 0) __syncthreads();     // prev chunk consumed
        // store prefetched chunk to smem
        {
            u64* xrow = &xs[xt][4 * xd4];
            xrow[0] = pk2(px.x, px.x);
            xrow[1] = pk2(px.y, px.y);
            xrow[2] = pk2(px.z, px.z);
            xrow[3] = pk2(px.w, px.w);
#pragma unroll
            for (int j = 0; j < 4; ++j) {
                int q = j * 256 + tid;
                int dd = q >> 5, c2 = q & 31;
                *(ulonglong2*)&Ws[dd][2 * c2] = pw[j];
            }
        }
        __syncthreads();
        // prefetch next chunk (latency hidden under compute below)
        if (ch < 31) {
            int base = (ch + 1) * 32;
            px = xsrc[base >> 2];
#pragma unroll
            for (int j = 0; j < 4; ++j) {
                int q = j * 256 + tid;
                int dd = q >> 5, c2 = q & 31;
                pw[j] = *(const ulonglong2*)&g_Wp[(size_t)(base + dd) * CPAIR + 2 * c2];
            }
        }
        // compute chunk
#pragma unroll 8
        for (int dd = 0; dd < 32; ++dd) {
            ulonglong2 w = *(const ulonglong2*)&Ws[dd][2 * cg];
#pragma unroll
            for (int i = 0; i < 4; ++i) {
                u64 xv = xs[tg + 8 * i][dd];
                FMA2(acc[i][0], w.x, xv);
                FMA2(acc[i][1], w.y, xv);
            }
        }
    }
#pragma unroll
    for (int i = 0; i < 4; ++i) {
        float4 o;
        upk2(o.x, o.y, acc[i][0]);
        upk2(o.z, o.w, acc[i][1]);
        *(float4*)&g_P[(size_t)(t0 + tg + 8 * i) * COLS + 4 * cg] = o;
    }
}

// -------- 5: similarity scan + argmax, smem-broadcast codebook --------
// Block: 128 thr, one head, 128 tokens (1 per thread). 512 blocks (all resident).
// Codebook in 8 chunks of 128 code pairs (16 KB smem); pair index warp-uniform
// -> broadcast LDS. 4 independent FMA2 chains per pair (depth 4) -> rt-bound.
__global__ __launch_bounds__(128) void sim_kernel(float* __restrict__ out) {
    __shared__ ulonglong2 cbs[1024];      // 16 KB: pair p -> units p*8..p*8+7
    int tid = threadIdx.x;
    int h = blockIdx.x & 7;
    int tb = blockIdx.x >> 3;             // 0..63
    int t = tb * 128 + tid;

    // load + duplicate q (16 u64)
    u64 qd[16];
    {
        const float4* q4 = (const float4*)&g_P[(size_t)t * COLS + h * E];
#pragma unroll
        for (int k = 0; k < 4; ++k) {
            float4 v = q4[k];
            qd[4 * k + 0] = pk2(v.x, v.x);
            qd[4 * k + 1] = pk2(v.y, v.y);
            qd[4 * k + 2] = pk2(v.z, v.z);
            qd[4 * k + 3] = pk2(v.w, v.w);
        }
    }

    const ulonglong2* src = (const ulonglong2*)(g_cbp + (size_t)h * NCP * E);
    float best = -3.402823466e38f;
    int idx = 0;

    for (int ch = 0; ch < 8; ++ch) {
        __syncthreads();                  // prev chunk fully consumed
#pragma unroll
        for (int j = 0; j < 8; ++j)       // coalesced 16 KB stage
            cbs[j * 128 + tid] = src[ch * 1024 + j * 128 + tid];
        __syncthreads();

        int cbase = ch * 256;             // first code index of chunk
#pragma unroll 4
        for (int p = 0; p < 128; ++p) {   // warp-uniform -> broadcast LDS
            ulonglong2 c0 = cbs[p * 8 + 0];
            ulonglong2 c1 = cbs[p * 8 + 1];
            ulonglong2 c2 = cbs[p * 8 + 2];
            ulonglong2 c3 = cbs[p * 8 + 3];
            ulonglong2 c4 = cbs[p * 8 + 4];
            ulonglong2 c5 = cbs[p * 8 + 5];
            ulonglong2 c6 = cbs[p * 8 + 6];
            ulonglong2 c7 = cbs[p * 8 + 7];
            u64 a0 = 0ull, a1 = 0ull, a2 = 0ull, a3 = 0ull;  // 4 chains, depth 4
            FMA2(a0, c0.x, qd[0]);  FMA2(a1, c0.y, qd[1]);
            FMA2(a2, c1.x, qd[2]);  FMA2(a3, c1.y, qd[3]);
            FMA2(a0, c2.x, qd[4]);  FMA2(a1, c2.y, qd[5]);
            FMA2(a2, c3.x, qd[6]);  FMA2(a3, c3.y, qd[7]);
            FMA2(a0, c4.x, qd[8]);  FMA2(a1, c4.y, qd[9]);
            FMA2(a2, c5.x, qd[10]); FMA2(a3, c5.y, qd[11]);
            FMA2(a0, c6.x, qd[12]); FMA2(a1, c6.y, qd[13]);
            FMA2(a2, c7.x, qd[14]); FMA2(a3, c7.y, qd[15]);
            ADD2(a0, a0, a1);
            ADD2(a2, a2, a3);
            ADD2(a0, a0, a2);
            float s0, s1;
            upk2(s0, s1, a0);
            float m = fmaxf(s0, s1);
            if (m > best) { best = m; idx = cbase + 2 * p + (s1 > s0 ? 1 : 0); }
        }
    }

    out[(size_t)t * H + h] = (float)idx;
}

extern "C" void kernel_launch(void* const* d_in, const int* in_sizes, int n_in,
                              void* d_out, int out_size) {
    const float* x = nullptr;
    const float* W = nullptr;
    const float* CB = nullptr;
    for (int i = 0; i < n_in; ++i) {
        long s = (long)in_sizes[i];
        if (s == 8388608L || s == 33554432L)      x  = (const float*)d_in[i];
        else if (s == 131072L || s == 524288L)    W  = (const float*)d_in[i];
        else if (s == 262144L || s == 1048576L)   CB = (const float*)d_in[i];
    }
    if (!x || !W || !CB) {
        if (n_in >= 3) {
            x  = (const float*)d_in[0];
            W  = (const float*)d_in[1];
            CB = (const float*)d_in[2];
        }
    }
    prepS_kernel<<<128, 256>>>(W);
    prepW_kernel<<<256, 256>>>(W);
    prepCB_kernel<<<32, 256>>>(CB);
    proj_kernel<<<256, 256>>>(x);
    sim_kernel<<<512, 128>>>((float*)d_out);
}

// round 9
// speedup vs baseline: 4.9886x; 1.2836x over previous
#include <cuda_runtime.h>
#include <cstdint>

// Problem constants
#define TOK 8192      // b*n tokens
#define D   1024
#define H   8
#define E   16
#define CS  2048
#define COLS (H*E)     // 128 projection columns
#define CPAIR (COLS/2) // 64 column pairs
#define NCP (CS/2)     // 1024 code pairs per head

typedef unsigned long long u64;

// -------- device scratch (static; no allocations allowed) --------
__device__ float g_S[COLS];                           // column sums of W
__device__ __align__(16) float2 g_Wp[D * CPAIR];      // W' = W - S/D, [d][colpair]      (512 KB)
__device__ __align__(16) float2 g_cbp[H * NCP * E];   // normalized cb, code-pair packed (1 MB)
__device__ __align__(16) float  g_P[TOK * COLS];      // projections [t][h*16+e]         (4 MB)

// -------- f32x2 helpers --------
__device__ __forceinline__ u64 pk2(float lo, float hi) {
    u64 r; asm("mov.b64 %0, {%1,%2};" : "=l"(r) : "f"(lo), "f"(hi)); return r;
}
__device__ __forceinline__ void upk2(float& lo, float& hi, u64 v) {
    asm("mov.b64 {%0,%1}, %2;" : "=f"(lo), "=f"(hi) : "l"(v));
}
#define FMA2(acc, a, b) asm("fma.rn.f32x2 %0, %1, %2, %0;" : "+l"(acc) : "l"(a), "l"(b))
#define ADD2(d, a, b)   asm("add.rn.f32x2 %0, %1, %2;" : "=l"(d) : "l"(a), "l"(b))

// -------- 1: column sums S[h,e] = sum_d W[h,d,e] --------
__global__ void prepS_kernel(const float* __restrict__ W) {
    int col = blockIdx.x;            // h*16+e, 128 blocks
    int h = col >> 4, e = col & 15;
    float s = 0.f;
    for (int d = threadIdx.x; d < D; d += 256)
        s += W[(h * D + d) * E + e];
    __shared__ float red[256];
    red[threadIdx.x] = s;
    __syncthreads();
    for (int off = 128; off > 0; off >>= 1) {
        if (threadIdx.x < off) red[threadIdx.x] += red[threadIdx.x + off];
        __syncthreads();
    }
    if (threadIdx.x == 0) g_S[col] = red[0];
}

// -------- 2: W'[d][cp] = (W - S/D) packed as column-pairs --------
__global__ void prepW_kernel(const float* __restrict__ W) {
    int i = blockIdx.x * 256 + threadIdx.x;   // 65536 = D*CPAIR
    int d = i >> 6, cp = i & 63;
    int h = cp >> 3, ep = cp & 7;
    const float invD = 1.0f / 1024.0f;
    float w0 = W[(h * D + d) * E + 2 * ep]     - g_S[h * E + 2 * ep]     * invD;
    float w1 = W[(h * D + d) * E + 2 * ep + 1] - g_S[h * E + 2 * ep + 1] * invD;
    g_Wp[i] = make_float2(w0, w1);
}

// -------- 3: normalized codebook, code-pair packed --------
// g_cbp[(h*NCP+cp)*E + e] = (cbn[2cp][e], cbn[2cp+1][e])
__global__ void prepCB_kernel(const float* __restrict__ CB) {
    int i = blockIdx.x * 256 + threadIdx.x;   // 8192 = H*NCP
    const float4* a4 = (const float4*)(CB + (size_t)i * 2 * E);
    float4 va[4], vb[4];
#pragma unroll
    for (int k = 0; k < 4; ++k) va[k] = a4[k];
#pragma unroll
    for (int k = 0; k < 4; ++k) vb[k] = a4[4 + k];
    float sa = 0.f, sb = 0.f;
#pragma unroll
    for (int k = 0; k < 4; ++k) {
        sa += va[k].x * va[k].x + va[k].y * va[k].y + va[k].z * va[k].z + va[k].w * va[k].w;
        sb += vb[k].x * vb[k].x + vb[k].y * vb[k].y + vb[k].z * vb[k].z + vb[k].w * vb[k].w;
    }
    float ra = 1.0f / sqrtf(sa + 1e-12f);
    float rb = 1.0f / sqrtf(sb + 1e-12f);
    float2* out = g_cbp + (size_t)i * E;
    const float* a = (const float*)va;
    const float* b = (const float*)vb;
#pragma unroll
    for (int e = 0; e < E; ++e)
        out[e] = make_float2(a[e] * ra, b[e] * rb);
}

// -------- 4: projection GEMM, f32x2, reg-prefetch, 128 thr / 32 tokens ----
// Thread (tg = tid&7, cg4 = tid>>3): tokens {tg,tg+8,tg+16,tg+24},
// colpairs {4cg4..4cg4+3}. Per dd: 16 FMA2 : 6 LDS.
__global__ __launch_bounds__(128) void proj_kernel(const float* __restrict__ x) {
    __shared__ u64    xs[32][34];   // [tok][dd] dup (x,x); pad 34
    __shared__ float2 Ws[32][64];   // [dd][colpair], 16 KB
    int t0 = blockIdx.x * 32;
    int tid = threadIdx.x;
    int tg = tid & 7;
    int cg4 = tid >> 3;             // 0..15

    // staging addresses (constant across chunks)
    int xtok = tid >> 2;            // token staged by this thread (0..31)
    int xf4  = tid & 3;             // float4 slot (dd = 4*xf4 and 16+4*xf4)
    const float4* xrow = (const float4*)(x + (size_t)(t0 + xtok) * D);

    u64 acc[4][4];
#pragma unroll
    for (int i = 0; i < 4; ++i)
#pragma unroll
        for (int k = 0; k < 4; ++k) acc[i][k] = 0ull;

    float4 px0, px1;
    ulonglong2 pw[8];

    // prefetch chunk 0
    px0 = xrow[xf4];
    px1 = xrow[4 + xf4];
#pragma unroll
    for (int j = 0; j < 8; ++j) {
        int q = j * 128 + tid;       // 0..1023
        int dd = q >> 5, c2 = q & 31;
        pw[j] = *(const ulonglong2*)&g_Wp[(size_t)dd * CPAIR + 2 * c2];
    }

    for (int ch = 0; ch < 32; ++ch) {
        if (ch > 0) __syncthreads();     // prev chunk consumed
        // store prefetched chunk
        {
            int d0 = 4 * xf4;
            xs[xtok][d0 + 0] = pk2(px0.x, px0.x);
            xs[xtok][d0 + 1] = pk2(px0.y, px0.y);
            xs[xtok][d0 + 2] = pk2(px0.z, px0.z);
            xs[xtok][d0 + 3] = pk2(px0.w, px0.w);
            xs[xtok][16 + d0 + 0] = pk2(px1.x, px1.x);
            xs[xtok][16 + d0 + 1] = pk2(px1.y, px1.y);
            xs[xtok][16 + d0 + 2] = pk2(px1.z, px1.z);
            xs[xtok][16 + d0 + 3] = pk2(px1.w, px1.w);
#pragma unroll
            for (int j = 0; j < 8; ++j) {
                int q = j * 128 + tid;
                int dd = q >> 5, c2 = q & 31;
                *(ulonglong2*)&Ws[dd][2 * c2] = pw[j];
            }
        }
        __syncthreads();
        // prefetch next chunk (hidden under compute)
        if (ch < 31) {
            int base = (ch + 1) * 32;
            px0 = xrow[(base >> 2) + xf4];
            px1 = xrow[(base >> 2) + 4 + xf4];
#pragma unroll
            for (int j = 0; j < 8; ++j) {
                int q = j * 128 + tid;
                int dd = q >> 5, c2 = q & 31;
                pw[j] = *(const ulonglong2*)&g_Wp[(size_t)(base + dd) * CPAIR + 2 * c2];
            }
        }
        // compute
#pragma unroll 4
        for (int dd = 0; dd < 32; ++dd) {
            ulonglong2 w0 = *(const ulonglong2*)&Ws[dd][4 * cg4];
            ulonglong2 w1 = *(const ulonglong2*)&Ws[dd][4 * cg4 + 2];
#pragma unroll
            for (int i = 0; i < 4; ++i) {
                u64 xv = xs[tg + 8 * i][dd];
                FMA2(acc[i][0], w0.x, xv);
                FMA2(acc[i][1], w0.y, xv);
                FMA2(acc[i][2], w1.x, xv);
                FMA2(acc[i][3], w1.y, xv);
            }
        }
    }
#pragma unroll
    for (int i = 0; i < 4; ++i) {
        float4 o0, o1;
        upk2(o0.x, o0.y, acc[i][0]);
        upk2(o0.z, o0.w, acc[i][1]);
        upk2(o1.x, o1.y, acc[i][2]);
        upk2(o1.z, o1.w, acc[i][3]);
        float* dst = &g_P[(size_t)(t0 + tg + 8 * i) * COLS + 8 * cg4];
        *(float4*)dst = o0;
        *(float4*)(dst + 4) = o1;
    }
}

// -------- 5: similarity scan + argmax, smem-broadcast, T=2 tokens/thread ----
// Grid: 128 CTAs = 16 token-tiles x 8 heads (single wave). 256 thr, 512 tokens
// per CTA. Codebook in 8 chunks of 128 code pairs (16 KB smem); pair index is
// warp-uniform -> broadcast LDS. 8 LDS.128/pair amortized over 2 tokens.
__global__ __launch_bounds__(256) void sim_kernel(float* __restrict__ out) {
    __shared__ ulonglong2 cbs[1024];      // 16 KB: pair p -> units p*8..p*8+7
    int tid = threadIdx.x;
    int h = blockIdx.x & 7;
    int tb = blockIdx.x >> 3;             // 0..15
    int t0 = tb * 512 + tid * 2;

    u64 qd0[16], qd1[16];
    {
        const float4* q4 = (const float4*)&g_P[(size_t)t0 * COLS + h * E];
#pragma unroll
        for (int k = 0; k < 4; ++k) {
            float4 v = q4[k];
            qd0[4 * k + 0] = pk2(v.x, v.x);
            qd0[4 * k + 1] = pk2(v.y, v.y);
            qd0[4 * k + 2] = pk2(v.z, v.z);
            qd0[4 * k + 3] = pk2(v.w, v.w);
        }
        q4 = (const float4*)&g_P[(size_t)(t0 + 1) * COLS + h * E];
#pragma unroll
        for (int k = 0; k < 4; ++k) {
            float4 v = q4[k];
            qd1[4 * k + 0] = pk2(v.x, v.x);
            qd1[4 * k + 1] = pk2(v.y, v.y);
            qd1[4 * k + 2] = pk2(v.z, v.z);
            qd1[4 * k + 3] = pk2(v.w, v.w);
        }
    }

    const ulonglong2* src = (const ulonglong2*)(g_cbp + (size_t)h * NCP * E);
    float best0 = -3.402823466e38f, best1 = -3.402823466e38f;
    int pb0 = 0, od0 = 0, pb1 = 0, od1 = 0;

    for (int ch = 0; ch < 8; ++ch) {
        __syncthreads();                  // prev chunk fully consumed
#pragma unroll
        for (int j = 0; j < 4; ++j)       // coalesced 16 KB stage
            cbs[j * 256 + tid] = src[ch * 1024 + j * 256 + tid];
        __syncthreads();

        int pbase = ch * 128;
#pragma unroll 2
        for (int p = 0; p < 128; ++p) {   // warp-uniform -> broadcast LDS
            ulonglong2 c0 = cbs[p * 8 + 0];
            ulonglong2 c1 = cbs[p * 8 + 1];
            ulonglong2 c2 = cbs[p * 8 + 2];
            ulonglong2 c3 = cbs[p * 8 + 3];
            ulonglong2 c4 = cbs[p * 8 + 4];
            ulonglong2 c5 = cbs[p * 8 + 5];
            ulonglong2 c6 = cbs[p * 8 + 6];
            ulonglong2 c7 = cbs[p * 8 + 7];
            // token 0: 4 chains
            u64 a0 = 0ull, a1 = 0ull, a2 = 0ull, a3 = 0ull;
            // token 1: 4 chains
            u64 b0 = 0ull, b1 = 0ull, b2 = 0ull, b3 = 0ull;
            FMA2(a0, c0.x, qd0[0]);  FMA2(b0, c0.x, qd1[0]);
            FMA2(a1, c0.y, qd0[1]);  FMA2(b1, c0.y, qd1[1]);
            FMA2(a2, c1.x, qd0[2]);  FMA2(b2, c1.x, qd1[2]);
            FMA2(a3, c1.y, qd0[3]);  FMA2(b3, c1.y, qd1[3]);
            FMA2(a0, c2.x, qd0[4]);  FMA2(b0, c2.x, qd1[4]);
            FMA2(a1, c2.y, qd0[5]);  FMA2(b1, c2.y, qd1[5]);
            FMA2(a2, c3.x, qd0[6]);  FMA2(b2, c3.x, qd1[6]);
            FMA2(a3, c3.y, qd0[7]);  FMA2(b3, c3.y, qd1[7]);
            FMA2(a0, c4.x, qd0[8]);  FMA2(b0, c4.x, qd1[8]);
            FMA2(a1, c4.y, qd0[9]);  FMA2(b1, c4.y, qd1[9]);
            FMA2(a2, c5.x, qd0[10]); FMA2(b2, c5.x, qd1[10]);
            FMA2(a3, c5.y, qd0[11]); FMA2(b3, c5.y, qd1[11]);
            FMA2(a0, c6.x, qd0[12]); FMA2(b0, c6.x, qd1[12]);
            FMA2(a1, c6.y, qd0[13]); FMA2(b1, c6.y, qd1[13]);
            FMA2(a2, c7.x, qd0[14]); FMA2(b2, c7.x, qd1[14]);
            FMA2(a3, c7.y, qd0[15]); FMA2(b3, c7.y, qd1[15]);
            ADD2(a0, a0, a1); ADD2(a2, a2, a3); ADD2(a0, a0, a2);
            ADD2(b0, b0, b1); ADD2(b2, b2, b3); ADD2(b0, b0, b2);
            float s0, s1;
            upk2(s0, s1, a0);
            float m = fmaxf(s0, s1);
            if (m > best0) { best0 = m; pb0 = pbase + p; od0 = (s1 > s0); }
            upk2(s0, s1, b0);
            m = fmaxf(s0, s1);
            if (m > best1) { best1 = m; pb1 = pbase + p; od1 = (s1 > s0); }
        }
    }

    out[(size_t)t0 * H + h]       = (float)(2 * pb0 + od0);
    out[(size_t)(t0 + 1) * H + h] = (float)(2 * pb1 + od1);
}

extern "C" void kernel_launch(void* const* d_in, const int* in_sizes, int n_in,
                              void* d_out, int out_size) {
    const float* x = nullptr;
    const float* W = nullptr;
    const float* CB = nullptr;
    for (int i = 0; i < n_in; ++i) {
        long s = (long)in_sizes[i];
        if (s == 8388608L || s == 33554432L)      x  = (const float*)d_in[i];
        else if (s == 131072L || s == 524288L)    W  = (const float*)d_in[i];
        else if (s == 262144L || s == 1048576L)   CB = (const float*)d_in[i];
    }
    if (!x || !W || !CB) {
        if (n_in >= 3) {
            x  = (const float*)d_in[0];
            W  = (const float*)d_in[1];
            CB = (const float*)d_in[2];
        }
    }
    prepS_kernel<<<128, 256>>>(W);
    prepW_kernel<<<256, 256>>>(W);
    prepCB_kernel<<<32, 256>>>(CB);
    proj_kernel<<<256, 128>>>(x);
    sim_kernel<<<128, 256>>>((float*)d_out);
}